// round 8
// baseline (speedup 1.0000x reference)
#include <cuda_runtime.h>
#include <cuda_bf16.h>
#include <math.h>
#include <stdint.h>

// NT-Xent loss via symmetric-triangle HMMA bf16 GEMM, software-pipelined
// epilogue (ex2 of tile t-1 hidden under MMA of tile t). N=4096, D=256.
// z' = z/||z|| * sqrt(10*log2e) (bf16) => acc = sim_ij * log2(e).
// loss_i = ln2*( lg2(sum_{j!=i} ex2(acc_ij)) - acc_pos ); out = mean.

#define NN 8192
#define HN 4096
#define DD 256
#define NBLK 64                     // 8192 / 128 row blocks
#define NFLAT 2080                  // 64*65/2 tiles
#define NCTA 130                    // 2080 / 16
#define TPC 16                      // tiles per CTA
#define C_SCALE 3.7982825615419297f // sqrt(10 * log2(e))
#define LN2 0.6931471805599453f

// ---- device scratch ----
__device__ __align__(512) __nv_bfloat16 g_zb[NN * DD];   // normalized z (4 MB)
__device__ float g_rowPart[NFLAT * 128];
__device__ float g_colPart[NFLAT * 128];
__device__ float g_posacc[NN];
__device__ float g_lossPartial[32];
__device__ int   g_ctr = 0;          // reset by finalizing block each launch

// ---------------------------------------------------------------------------
__device__ __forceinline__ uint32_t smem_u32(const void* p) {
    uint32_t a;
    asm("{ .reg .u64 t; cvta.to.shared.u64 t, %1; cvt.u32.u64 %0, t; }" : "=r"(a) : "l"(p));
    return a;
}
__device__ __forceinline__ void cp16(uint32_t smem_dst, const void* gsrc) {
    asm volatile("cp.async.cg.shared.global [%0], [%1], 16;" :: "r"(smem_dst), "l"(gsrc));
}
#define CP_COMMIT() asm volatile("cp.async.commit_group;" ::: "memory")
#define CP_WAIT0()  asm volatile("cp.async.wait_group 0;" ::: "memory")

__device__ __forceinline__ float ex2f(float x) {
    float y; asm("ex2.approx.f32 %0, %1;" : "=f"(y) : "f"(x)); return y;
}
__device__ __forceinline__ float lg2f(float x) {
    float y; asm("lg2.approx.f32 %0, %1;" : "=f"(y) : "f"(x)); return y;
}
__device__ __forceinline__ void ldsm_x4(uint32_t& r0, uint32_t& r1, uint32_t& r2,
                                        uint32_t& r3, uint32_t addr) {
    asm volatile("ldmatrix.sync.aligned.m8n8.x4.shared.b16 {%0,%1,%2,%3}, [%4];"
                 : "=r"(r0), "=r"(r1), "=r"(r2), "=r"(r3) : "r"(addr));
}
__device__ __forceinline__ void mma16816(float* c, const uint32_t* a, const uint32_t* b) {
    asm volatile(
        "mma.sync.aligned.m16n8k16.row.col.f32.bf16.bf16.f32 "
        "{%0,%1,%2,%3}, {%4,%5,%6,%7}, {%8,%9}, {%0,%1,%2,%3};"
        : "+f"(c[0]), "+f"(c[1]), "+f"(c[2]), "+f"(c[3])
        : "r"(a[0]), "r"(a[1]), "r"(a[2]), "r"(a[3]), "r"(b[0]), "r"(b[1]));
}

// ---------------------------------------------------------------------------
// Kernel A: normalize rows, scale by sqrt(10*log2e), emit bf16. Warp per row.
// ---------------------------------------------------------------------------
__global__ __launch_bounds__(256) void normalize_kernel(
    const float* __restrict__ z1, const float* __restrict__ z2)
{
    const int wid = threadIdx.x >> 5, lid = threadIdx.x & 31;
    const int row = blockIdx.x * 8 + wid;
    const float* src = (row < HN) ? (z1 + (size_t)row * DD)
                                  : (z2 + (size_t)(row - HN) * DD);
    float4 v0 = reinterpret_cast<const float4*>(src)[lid];
    float4 v1 = reinterpret_cast<const float4*>(src)[lid + 32];
    float ss = v0.x * v0.x + v0.y * v0.y + v0.z * v0.z + v0.w * v0.w
             + v1.x * v1.x + v1.y * v1.y + v1.z * v1.z + v1.w * v1.w;
    #pragma unroll
    for (int off = 16; off > 0; off >>= 1) ss += __shfl_xor_sync(0xffffffffu, ss, off);
    float s = C_SCALE / fmaxf(sqrtf(ss), 1e-12f);
    __nv_bfloat162* dst = reinterpret_cast<__nv_bfloat162*>(g_zb + (size_t)row * DD);
    dst[2 * lid + 0]      = __floats2bfloat162_rn(v0.x * s, v0.y * s);
    dst[2 * lid + 1]      = __floats2bfloat162_rn(v0.z * s, v0.w * s);
    dst[64 + 2 * lid + 0] = __floats2bfloat162_rn(v1.x * s, v1.y * s);
    dst[64 + 2 * lid + 1] = __floats2bfloat162_rn(v1.z * s, v1.w * s);
}

// ---------------------------------------------------------------------------
// Kernel B: triangle-tile HMMA GEMM, pipelined ex2 epilogue.
// 130 CTAs x 16 tiles. SMEM: A resident 64KB + B double 128KB + reduce 3KB.
// ---------------------------------------------------------------------------
__global__ __launch_bounds__(256, 1) void sim_mma_kernel()
{
    extern __shared__ char smem[];
    const uint32_t sb = smem_u32(smem);
    const uint32_t A_BASE = sb, B_BASE = sb + 65536, BSZ = 65536;
    float* rowred = reinterpret_cast<float*>(smem + 196608);   // [2][128]
    float* colred = reinterpret_cast<float*>(smem + 197632);   // [4][128]

    const int tid = threadIdx.x, wid = tid >> 5, lid = tid & 31;
    const int wy = wid >> 1, wx = wid & 1;       // warp grid 4 (m) x 2 (n)
    const int my = wy * 32, nx = wx * 64;

    const int f0 = blockIdx.x * TPC;
    int I = 0, S = 0;
    while (S + (NBLK - I) <= f0) { S += NBLK - I; ++I; }
    int J = I + (f0 - S);

    const int sub = lid >> 3, lr = lid & 7;
    const int rowA0 = my + ((sub & 1) << 3) + lr;
    const int cAoff = sub >> 1;
    const int rowB0 = nx + ((sub >> 1) << 3) + lr;
    const int cBoff = sub & 1;

    int curI = -1, bufc = 0, prevF = 0;
    bool pend = false, prevFast = false;

    float re[4] = {0.f, 0.f, 0.f, 0.f};
    float cs[16];
    #pragma unroll
    for (int k = 0; k < 16; ++k) cs[k] = 0.f;

    auto loadA = [&](int Ii) {
        for (int i = tid; i < 4096; i += 256) {
            int r = i >> 5, c = i & 31;
            cp16(A_BASE + r * 512 + ((c ^ (r & 7)) << 4),
                 &g_zb[(size_t)(Ii * 128 + r) * DD + c * 8]);
        }
    };
    auto loadB = [&](int buf, int Jj) {
        for (int i = tid; i < 4096; i += 256) {
            int r = i >> 5, c = i & 31;
            cp16(B_BASE + buf * BSZ + r * 512 + ((c ^ (r & 7)) << 4),
                 &g_zb[(size_t)(Jj * 128 + r) * DD + c * 8]);
        }
    };

    // reduce re/cs across warps, store partials for flat tile f, reset sums.
    auto reduce_store = [&](int f, bool wantCols) {
        #pragma unroll
        for (int e = 0; e < 4; ++e) {
            re[e] += __shfl_xor_sync(0xffffffffu, re[e], 1);
            re[e] += __shfl_xor_sync(0xffffffffu, re[e], 2);
        }
        if ((lid & 3) == 0) {
            #pragma unroll
            for (int e = 0; e < 4; ++e) {
                int rl = my + 16 * (e >> 1) + 8 * (e & 1) + (lid >> 2);
                rowred[wx * 128 + rl] = re[e];
            }
        }
        if (wantCols) {
            #pragma unroll
            for (int k = 0; k < 16; ++k) {
                cs[k] += __shfl_xor_sync(0xffffffffu, cs[k], 4);
                cs[k] += __shfl_xor_sync(0xffffffffu, cs[k], 8);
                cs[k] += __shfl_xor_sync(0xffffffffu, cs[k], 16);
            }
            if (lid < 4) {
                #pragma unroll
                for (int k = 0; k < 16; ++k) {
                    int cl = nx + 8 * (k >> 1) + 2 * lid + (k & 1);
                    colred[wy * 128 + cl] = cs[k];
                }
            }
        }
        __syncthreads();
        if (tid < 128) {
            g_rowPart[(size_t)f * 128 + tid] = rowred[tid] + rowred[128 + tid];
            if (wantCols)
                g_colPart[(size_t)f * 128 + tid] =
                    colred[tid] + colred[128 + tid] + colred[256 + tid] + colred[384 + tid];
        }
        __syncthreads();
        #pragma unroll
        for (int e = 0; e < 4; ++e) re[e] = 0.f;
        #pragma unroll
        for (int k = 0; k < 16; ++k) cs[k] = 0.f;
    };

    auto tile_body = [&](auto& cur, auto& prv, int t) {
        if (!pend) {
            if (t) __syncthreads();
            if (I != curI) { loadA(I); curI = I; }
            loadB(bufc, J);
            CP_COMMIT();
        }
        CP_WAIT0();
        __syncthreads();
        int nI = I, nJ = J + 1;
        if (nJ == NBLK) { ++nI; nJ = nI; }
        if (t + 1 < TPC && nI == I) {
            loadB(bufc ^ 1, nJ);
            CP_COMMIT();
            pend = true;
        } else pend = false;

        const uint32_t Bb = B_BASE + bufc * BSZ;
        #pragma unroll
        for (int i = 0; i < 2; ++i)
            #pragma unroll
            for (int j = 0; j < 8; ++j)
                #pragma unroll
                for (int q = 0; q < 4; ++q) cur[i][j][q] = 0.f;

        #pragma unroll
        for (int ks = 0; ks < 16; ++ks) {
            const int c0 = 2 * ks;
            uint32_t a[2][4], b[8][2];
            #pragma unroll
            for (int i = 0; i < 2; ++i) {
                int row = rowA0 + 16 * i;
                ldsm_x4(a[i][0], a[i][1], a[i][2], a[i][3],
                        A_BASE + row * 512 + (((c0 + cAoff) ^ (row & 7)) << 4));
            }
            #pragma unroll
            for (int jj = 0; jj < 4; ++jj) {
                int row = rowB0 + 16 * jj;
                ldsm_x4(b[2 * jj][0], b[2 * jj][1], b[2 * jj + 1][0], b[2 * jj + 1][1],
                        Bb + row * 512 + (((c0 + cBoff) ^ (row & 7)) << 4));
            }
            #pragma unroll
            for (int i = 0; i < 2; ++i)
                #pragma unroll
                for (int j = 0; j < 8; ++j)
                    mma16816(cur[i][j], a[i], b[j]);
            // pipelined epilogue chunk: one cell of the previous tile per k-step
            if (prevFast) {
                const int pi = ks >> 3, pj = ks & 7;
                float e0 = ex2f(prv[pi][pj][0]), e1 = ex2f(prv[pi][pj][1]);
                float e2 = ex2f(prv[pi][pj][2]), e3 = ex2f(prv[pi][pj][3]);
                re[2 * pi]     += e0 + e1;
                re[2 * pi + 1] += e2 + e3;
                cs[2 * pj]     += e0 + e2;
                cs[2 * pj + 1] += e1 + e3;
            }
        }
        if (prevFast) reduce_store(prevF, true);

        const bool diag  = (I == J);
        const bool postl = (J == I + 32);
        const int  f     = f0 + t;
        if (diag) {
            const int colT = J * 128 + nx + 2 * (lid & 3);
            #pragma unroll
            for (int i = 0; i < 2; ++i) {
                const int gr0 = I * 128 + my + 16 * i + (lid >> 2);
                const int gr1 = gr0 + 8;
                #pragma unroll
                for (int j = 0; j < 8; ++j) {
                    const int gc0 = colT + 8 * j, gc1 = gc0 + 1;
                    if (gc0 != gr0) re[2 * i]     += ex2f(cur[i][j][0]);
                    if (gc1 != gr0) re[2 * i]     += ex2f(cur[i][j][1]);
                    if (gc0 != gr1) re[2 * i + 1] += ex2f(cur[i][j][2]);
                    if (gc1 != gr1) re[2 * i + 1] += ex2f(cur[i][j][3]);
                }
            }
            reduce_store(f, false);
            prevFast = false;
        } else if (postl) {
            const int colT = J * 128 + nx + 2 * (lid & 3);
            #pragma unroll
            for (int i = 0; i < 2; ++i) {
                const int gr0 = I * 128 + my + 16 * i + (lid >> 2);
                const int gr1 = gr0 + 8;
                const int p0 = gr0 ^ HN, p1 = gr1 ^ HN;
                #pragma unroll
                for (int j = 0; j < 8; ++j) {
                    const int gc0 = colT + 8 * j, gc1 = gc0 + 1;
                    float e0 = ex2f(cur[i][j][0]), e1 = ex2f(cur[i][j][1]);
                    float e2 = ex2f(cur[i][j][2]), e3 = ex2f(cur[i][j][3]);
                    re[2 * i]     += e0 + e1;
                    re[2 * i + 1] += e2 + e3;
                    cs[2 * j]     += e0 + e2;
                    cs[2 * j + 1] += e1 + e3;
                    if (gc0 == p0) { g_posacc[gr0] = cur[i][j][0]; g_posacc[p0] = cur[i][j][0]; }
                    if (gc1 == p0) { g_posacc[gr0] = cur[i][j][1]; g_posacc[p0] = cur[i][j][1]; }
                    if (gc0 == p1) { g_posacc[gr1] = cur[i][j][2]; g_posacc[p1] = cur[i][j][2]; }
                    if (gc1 == p1) { g_posacc[gr1] = cur[i][j][3]; g_posacc[p1] = cur[i][j][3]; }
                }
            }
            reduce_store(f, true);
            prevFast = false;
        } else {
            prevFast = true;
            prevF = f;
        }

        if (pend) bufc ^= 1;
        I = nI; J = nJ;
    };

    float acc0[2][8][4], acc1[2][8][4];
    for (int tt = 0; tt < TPC / 2; ++tt) {
        tile_body(acc0, acc1, 2 * tt);
        tile_body(acc1, acc0, 2 * tt + 1);
    }
    // trailing flush: tile 15 (cur = acc1) may still be deferred
    if (prevFast) {
        #pragma unroll
        for (int pi = 0; pi < 2; ++pi)
            #pragma unroll
            for (int pj = 0; pj < 8; ++pj) {
                float e0 = ex2f(acc1[pi][pj][0]), e1 = ex2f(acc1[pi][pj][1]);
                float e2 = ex2f(acc1[pi][pj][2]), e3 = ex2f(acc1[pi][pj][3]);
                re[2 * pi]     += e0 + e1;
                re[2 * pi + 1] += e2 + e3;
                cs[2 * pj]     += e0 + e2;
                cs[2 * pj + 1] += e1 + e3;
            }
        reduce_store(prevF, true);
    }
}

// ---------------------------------------------------------------------------
// Kernel C: per-row loss + global reduce; last-done block finalizes.
// ---------------------------------------------------------------------------
__global__ __launch_bounds__(256) void loss_reduce_kernel(float* __restrict__ out)
{
    const int r  = blockIdx.x * 256 + threadIdx.x;
    const int Ir = r >> 7, lr = r & 127;

    float tot = 0.f;
    const int base = NBLK * Ir - (Ir * (Ir - 1)) / 2;   // S(Ir)
    for (int Jt = Ir; Jt < NBLK; ++Jt)
        tot += g_rowPart[(size_t)(base + Jt - Ir) * 128 + lr];
    int Sp = 0;
    for (int I2 = 0; I2 < Ir; ++I2) {
        tot += g_colPart[(size_t)(Sp + Ir - I2) * 128 + lr];
        Sp += NBLK - I2;
    }
    float loss = lg2f(tot) - g_posacc[r];

    __shared__ float sm[256];
    __shared__ int last;
    sm[threadIdx.x] = loss;
    __syncthreads();
    #pragma unroll
    for (int off = 128; off > 0; off >>= 1) {
        if (threadIdx.x < off) sm[threadIdx.x] += sm[threadIdx.x + off];
        __syncthreads();
    }
    if (threadIdx.x == 0) {
        g_lossPartial[blockIdx.x] = sm[0];
        __threadfence();
        last = (atomicAdd(&g_ctr, 1) == 31);
    }
    __syncthreads();
    if (last && threadIdx.x < 32) {
        __threadfence();
        float v = g_lossPartial[threadIdx.x];
        #pragma unroll
        for (int off = 16; off > 0; off >>= 1)
            v += __shfl_down_sync(0xffffffffu, v, off);
        if (threadIdx.x == 0) { out[0] = v * (LN2 / (float)NN); g_ctr = 0; }
    }
}

// ---------------------------------------------------------------------------
extern "C" void kernel_launch(void* const* d_in, const int* in_sizes, int n_in,
                              void* d_out, int out_size)
{
    (void)in_sizes; (void)n_in; (void)out_size;
    const float* z1 = (const float*)d_in[0];
    const float* z2 = (const float*)d_in[1];
    float* out = (float*)d_out;

    static int smem_set = 0;
    const int SMEM_BYTES = 196608 + 3072;
    if (!smem_set) {
        cudaFuncSetAttribute(sim_mma_kernel,
                             cudaFuncAttributeMaxDynamicSharedMemorySize, SMEM_BYTES);
        smem_set = 1;
    }

    normalize_kernel<<<NN / 8, 256>>>(z1, z2);
    sim_mma_kernel<<<NCTA, 256, SMEM_BYTES>>>();
    loss_reduce_kernel<<<32, 256>>>(out);
}

// round 9
// speedup vs baseline: 1.6208x; 1.6208x over previous
#include <cuda_runtime.h>
#include <cuda_bf16.h>
#include <math.h>
#include <stdint.h>

// NT-Xent loss via symmetric-triangle HMMA bf16 GEMM, software-pipelined
// epilogue (ex2 of tile t-1 hidden under MMA of tile t). 512 threads,
// warp tile 32x32 => 32-reg accumulators so double-buffering fits the RF.
// z' = z/||z|| * sqrt(10*log2e) (bf16) => acc = sim_ij * log2(e).
// loss_i = ln2*( lg2(sum_{j!=i} ex2(acc_ij)) - acc_pos ); out = mean.

#define NN 8192
#define HN 4096
#define DD 256
#define NBLK 64                     // 8192 / 128 row blocks
#define NFLAT 2080                  // 64*65/2 tiles
#define NCTA 130                    // 2080 / 16
#define TPC 16                      // tiles per CTA
#define C_SCALE 3.7982825615419297f // sqrt(10 * log2(e))
#define LN2 0.6931471805599453f

// ---- device scratch ----
__device__ __align__(512) __nv_bfloat16 g_zb[NN * DD];   // normalized z (4 MB)
__device__ float g_rowPart[NFLAT * 128];
__device__ float g_colPart[NFLAT * 128];
__device__ float g_posacc[NN];
__device__ float g_lossPartial[32];
__device__ int   g_ctr = 0;

// ---------------------------------------------------------------------------
__device__ __forceinline__ uint32_t smem_u32(const void* p) {
    uint32_t a;
    asm("{ .reg .u64 t; cvta.to.shared.u64 t, %1; cvt.u32.u64 %0, t; }" : "=r"(a) : "l"(p));
    return a;
}
__device__ __forceinline__ void cp16(uint32_t smem_dst, const void* gsrc) {
    asm volatile("cp.async.cg.shared.global [%0], [%1], 16;" :: "r"(smem_dst), "l"(gsrc));
}
#define CP_COMMIT() asm volatile("cp.async.commit_group;" ::: "memory")
#define CP_WAIT0()  asm volatile("cp.async.wait_group 0;" ::: "memory")

__device__ __forceinline__ float ex2f(float x) {
    float y; asm("ex2.approx.f32 %0, %1;" : "=f"(y) : "f"(x)); return y;
}
__device__ __forceinline__ float lg2f(float x) {
    float y; asm("lg2.approx.f32 %0, %1;" : "=f"(y) : "f"(x)); return y;
}
__device__ __forceinline__ void ldsm_x4(uint32_t& r0, uint32_t& r1, uint32_t& r2,
                                        uint32_t& r3, uint32_t addr) {
    asm volatile("ldmatrix.sync.aligned.m8n8.x4.shared.b16 {%0,%1,%2,%3}, [%4];"
                 : "=r"(r0), "=r"(r1), "=r"(r2), "=r"(r3) : "r"(addr));
}
__device__ __forceinline__ void mma16816(float* c, const uint32_t* a, const uint32_t* b) {
    asm volatile(
        "mma.sync.aligned.m16n8k16.row.col.f32.bf16.bf16.f32 "
        "{%0,%1,%2,%3}, {%4,%5,%6,%7}, {%8,%9}, {%0,%1,%2,%3};"
        : "+f"(c[0]), "+f"(c[1]), "+f"(c[2]), "+f"(c[3])
        : "r"(a[0]), "r"(a[1]), "r"(a[2]), "r"(a[3]), "r"(b[0]), "r"(b[1]));
}

// ---------------------------------------------------------------------------
// Kernel A: normalize rows, scale by sqrt(10*log2e), emit bf16. Warp per row.
// ---------------------------------------------------------------------------
__global__ __launch_bounds__(256) void normalize_kernel(
    const float* __restrict__ z1, const float* __restrict__ z2)
{
    const int wid = threadIdx.x >> 5, lid = threadIdx.x & 31;
    const int row = blockIdx.x * 8 + wid;
    const float* src = (row < HN) ? (z1 + (size_t)row * DD)
                                  : (z2 + (size_t)(row - HN) * DD);
    float4 v0 = reinterpret_cast<const float4*>(src)[lid];
    float4 v1 = reinterpret_cast<const float4*>(src)[lid + 32];
    float ss = v0.x * v0.x + v0.y * v0.y + v0.z * v0.z + v0.w * v0.w
             + v1.x * v1.x + v1.y * v1.y + v1.z * v1.z + v1.w * v1.w;
    #pragma unroll
    for (int off = 16; off > 0; off >>= 1) ss += __shfl_xor_sync(0xffffffffu, ss, off);
    float s = C_SCALE / fmaxf(sqrtf(ss), 1e-12f);
    __nv_bfloat162* dst = reinterpret_cast<__nv_bfloat162*>(g_zb + (size_t)row * DD);
    dst[2 * lid + 0]      = __floats2bfloat162_rn(v0.x * s, v0.y * s);
    dst[2 * lid + 1]      = __floats2bfloat162_rn(v0.z * s, v0.w * s);
    dst[64 + 2 * lid + 0] = __floats2bfloat162_rn(v1.x * s, v1.y * s);
    dst[64 + 2 * lid + 1] = __floats2bfloat162_rn(v1.z * s, v1.w * s);
}

// ---------------------------------------------------------------------------
// Kernel B: triangle-tile HMMA GEMM, pipelined ex2 epilogue.
// 130 CTAs x 16 tiles. 512 threads, warp grid 4(m) x 4(n), warp tile 32x32.
// SMEM: A resident 64KB + B double 128KB + reduce 4KB.
// ---------------------------------------------------------------------------
__global__ __launch_bounds__(512, 1) void sim_mma_kernel()
{
    extern __shared__ char smem[];
    const uint32_t sb = smem_u32(smem);
    const uint32_t A_BASE = sb, B_BASE = sb + 65536, BSZ = 65536;
    float* rowred = reinterpret_cast<float*>(smem + 196608);   // [4][128]
    float* colred = reinterpret_cast<float*>(smem + 198656);   // [4][128]

    const int tid = threadIdx.x, wid = tid >> 5, lid = tid & 31;
    const int wy = wid >> 2, wx = wid & 3;       // warp grid 4 (m) x 4 (n)
    const int my = wy * 32, nx = wx * 32;

    const int f0 = blockIdx.x * TPC;
    int I = 0, S = 0;
    while (S + (NBLK - I) <= f0) { S += NBLK - I; ++I; }
    int J = I + (f0 - S);

    const int sub = lid >> 3, lr = lid & 7;
    const int rowA0 = my + ((sub & 1) << 3) + lr;
    const int cAoff = sub >> 1;
    const int rowB0 = nx + ((sub >> 1) << 3) + lr;
    const int cBoff = sub & 1;

    int curI = -1, bufc = 0, prevF = 0;
    bool pend = false, prevFast = false;

    float re[4] = {0.f, 0.f, 0.f, 0.f};
    float cs[8];
    #pragma unroll
    for (int k = 0; k < 8; ++k) cs[k] = 0.f;

    auto loadA = [&](int Ii) {
        for (int i = tid; i < 4096; i += 512) {
            int r = i >> 5, c = i & 31;
            cp16(A_BASE + r * 512 + ((c ^ (r & 7)) << 4),
                 &g_zb[(size_t)(Ii * 128 + r) * DD + c * 8]);
        }
    };
    auto loadB = [&](int buf, int Jj) {
        for (int i = tid; i < 4096; i += 512) {
            int r = i >> 5, c = i & 31;
            cp16(B_BASE + buf * BSZ + r * 512 + ((c ^ (r & 7)) << 4),
                 &g_zb[(size_t)(Jj * 128 + r) * DD + c * 8]);
        }
    };

    auto reduce_store = [&](int f, bool wantCols) {
        #pragma unroll
        for (int e = 0; e < 4; ++e) {
            re[e] += __shfl_xor_sync(0xffffffffu, re[e], 1);
            re[e] += __shfl_xor_sync(0xffffffffu, re[e], 2);
        }
        if ((lid & 3) == 0) {
            #pragma unroll
            for (int e = 0; e < 4; ++e) {
                int rl = my + 16 * (e >> 1) + 8 * (e & 1) + (lid >> 2);
                rowred[wx * 128 + rl] = re[e];
            }
        }
        if (wantCols) {
            #pragma unroll
            for (int k = 0; k < 8; ++k) {
                cs[k] += __shfl_xor_sync(0xffffffffu, cs[k], 4);
                cs[k] += __shfl_xor_sync(0xffffffffu, cs[k], 8);
                cs[k] += __shfl_xor_sync(0xffffffffu, cs[k], 16);
            }
            if (lid < 4) {
                #pragma unroll
                for (int k = 0; k < 8; ++k) {
                    int cl = nx + 8 * (k >> 1) + 2 * lid + (k & 1);
                    colred[wy * 128 + cl] = cs[k];
                }
            }
        }
        __syncthreads();
        if (tid < 128) {
            g_rowPart[(size_t)f * 128 + tid] =
                rowred[tid] + rowred[128 + tid] + rowred[256 + tid] + rowred[384 + tid];
            if (wantCols)
                g_colPart[(size_t)f * 128 + tid] =
                    colred[tid] + colred[128 + tid] + colred[256 + tid] + colred[384 + tid];
        }
        __syncthreads();
        #pragma unroll
        for (int e = 0; e < 4; ++e) re[e] = 0.f;
        #pragma unroll
        for (int k = 0; k < 8; ++k) cs[k] = 0.f;
    };

    auto tile_body = [&](float (&cur)[2][4][4], float (&prv)[2][4][4], int t) {
        if (!pend) {
            if (t) __syncthreads();
            if (I != curI) { loadA(I); curI = I; }
            loadB(bufc, J);
            CP_COMMIT();
        }
        CP_WAIT0();
        __syncthreads();
        int nI = I, nJ = J + 1;
        if (nJ == NBLK) { ++nI; nJ = nI; }
        if (t + 1 < TPC && nI == I) {
            loadB(bufc ^ 1, nJ);
            CP_COMMIT();
            pend = true;
        } else pend = false;

        const uint32_t Bb = B_BASE + bufc * BSZ;
        #pragma unroll
        for (int i = 0; i < 2; ++i)
            #pragma unroll
            for (int j = 0; j < 4; ++j)
                #pragma unroll
                for (int q = 0; q < 4; ++q) cur[i][j][q] = 0.f;

        #pragma unroll
        for (int ks = 0; ks < 16; ++ks) {
            const int c0 = 2 * ks;
            uint32_t a[2][4], b[4][2];
            #pragma unroll
            for (int i = 0; i < 2; ++i) {
                int row = rowA0 + 16 * i;
                ldsm_x4(a[i][0], a[i][1], a[i][2], a[i][3],
                        A_BASE + row * 512 + (((c0 + cAoff) ^ (row & 7)) << 4));
            }
            #pragma unroll
            for (int jj = 0; jj < 2; ++jj) {
                int row = rowB0 + 16 * jj;
                ldsm_x4(b[2 * jj][0], b[2 * jj][1], b[2 * jj + 1][0], b[2 * jj + 1][1],
                        Bb + row * 512 + (((c0 + cBoff) ^ (row & 7)) << 4));
            }
            #pragma unroll
            for (int i = 0; i < 2; ++i)
                #pragma unroll
                for (int j = 0; j < 4; ++j)
                    mma16816(cur[i][j], a[i], b[j]);
            // pipelined epilogue: one cell of the previous tile every 2 steps
            if (prevFast && (ks & 1) == 0) {
                const int cell = ks >> 1;        // 0..7
                const int pi = cell >> 2, pj = cell & 3;
                float e0 = ex2f(prv[pi][pj][0]), e1 = ex2f(prv[pi][pj][1]);
                float e2 = ex2f(prv[pi][pj][2]), e3 = ex2f(prv[pi][pj][3]);
                re[2 * pi]     += e0 + e1;
                re[2 * pi + 1] += e2 + e3;
                cs[2 * pj]     += e0 + e2;
                cs[2 * pj + 1] += e1 + e3;
            }
        }
        if (prevFast) reduce_store(prevF, true);

        const bool diag  = (I == J);
        const bool postl = (J == I + 32);
        const int  f     = f0 + t;
        if (diag) {
            const int colT = J * 128 + nx + 2 * (lid & 3);
            #pragma unroll
            for (int i = 0; i < 2; ++i) {
                const int gr0 = I * 128 + my + 16 * i + (lid >> 2);
                const int gr1 = gr0 + 8;
                #pragma unroll
                for (int j = 0; j < 4; ++j) {
                    const int gc0 = colT + 8 * j, gc1 = gc0 + 1;
                    if (gc0 != gr0) re[2 * i]     += ex2f(cur[i][j][0]);
                    if (gc1 != gr0) re[2 * i]     += ex2f(cur[i][j][1]);
                    if (gc0 != gr1) re[2 * i + 1] += ex2f(cur[i][j][2]);
                    if (gc1 != gr1) re[2 * i + 1] += ex2f(cur[i][j][3]);
                }
            }
            reduce_store(f, false);
            prevFast = false;
        } else if (postl) {
            const int colT = J * 128 + nx + 2 * (lid & 3);
            #pragma unroll
            for (int i = 0; i < 2; ++i) {
                const int gr0 = I * 128 + my + 16 * i + (lid >> 2);
                const int gr1 = gr0 + 8;
                const int p0 = gr0 ^ HN, p1 = gr1 ^ HN;
                #pragma unroll
                for (int j = 0; j < 4; ++j) {
                    const int gc0 = colT + 8 * j, gc1 = gc0 + 1;
                    float e0 = ex2f(cur[i][j][0]), e1 = ex2f(cur[i][j][1]);
                    float e2 = ex2f(cur[i][j][2]), e3 = ex2f(cur[i][j][3]);
                    re[2 * i]     += e0 + e1;
                    re[2 * i + 1] += e2 + e3;
                    cs[2 * j]     += e0 + e2;
                    cs[2 * j + 1] += e1 + e3;
                    if (gc0 == p0) { g_posacc[gr0] = cur[i][j][0]; g_posacc[p0] = cur[i][j][0]; }
                    if (gc1 == p0) { g_posacc[gr0] = cur[i][j][1]; g_posacc[p0] = cur[i][j][1]; }
                    if (gc0 == p1) { g_posacc[gr1] = cur[i][j][2]; g_posacc[p1] = cur[i][j][2]; }
                    if (gc1 == p1) { g_posacc[gr1] = cur[i][j][3]; g_posacc[p1] = cur[i][j][3]; }
                }
            }
            reduce_store(f, true);
            prevFast = false;
        } else {
            prevFast = true;
            prevF = f;
        }

        if (pend) bufc ^= 1;
        I = nI; J = nJ;
    };

    float acc0[2][4][4], acc1[2][4][4];
    for (int tt = 0; tt < TPC / 2; ++tt) {
        tile_body(acc0, acc1, 2 * tt);
        tile_body(acc1, acc0, 2 * tt + 1);
    }
    // trailing flush: tile 15 (cur = acc1) may still be deferred
    if (prevFast) {
        #pragma unroll
        for (int pi = 0; pi < 2; ++pi)
            #pragma unroll
            for (int pj = 0; pj < 4; ++pj) {
                float e0 = ex2f(acc1[pi][pj][0]), e1 = ex2f(acc1[pi][pj][1]);
                float e2 = ex2f(acc1[pi][pj][2]), e3 = ex2f(acc1[pi][pj][3]);
                re[2 * pi]     += e0 + e1;
                re[2 * pi + 1] += e2 + e3;
                cs[2 * pj]     += e0 + e2;
                cs[2 * pj + 1] += e1 + e3;
            }
        reduce_store(prevF, true);
    }
}

// ---------------------------------------------------------------------------
// Kernel C: per-row loss + global reduce; last-done block finalizes.
// ---------------------------------------------------------------------------
__global__ __launch_bounds__(256) void loss_reduce_kernel(float* __restrict__ out)
{
    const int r  = blockIdx.x * 256 + threadIdx.x;
    const int Ir = r >> 7, lr = r & 127;

    float tot = 0.f;
    const int base = NBLK * Ir - (Ir * (Ir - 1)) / 2;   // S(Ir)
    for (int Jt = Ir; Jt < NBLK; ++Jt)
        tot += g_rowPart[(size_t)(base + Jt - Ir) * 128 + lr];
    int Sp = 0;
    for (int I2 = 0; I2 < Ir; ++I2) {
        tot += g_colPart[(size_t)(Sp + Ir - I2) * 128 + lr];
        Sp += NBLK - I2;
    }
    float loss = lg2f(tot) - g_posacc[r];

    __shared__ float sm[256];
    __shared__ int last;
    sm[threadIdx.x] = loss;
    __syncthreads();
    #pragma unroll
    for (int off = 128; off > 0; off >>= 1) {
        if (threadIdx.x < off) sm[threadIdx.x] += sm[threadIdx.x + off];
        __syncthreads();
    }
    if (threadIdx.x == 0) {
        g_lossPartial[blockIdx.x] = sm[0];
        __threadfence();
        last = (atomicAdd(&g_ctr, 1) == 31);
    }
    __syncthreads();
    if (last && threadIdx.x < 32) {
        __threadfence();
        float v = g_lossPartial[threadIdx.x];
        #pragma unroll
        for (int off = 16; off > 0; off >>= 1)
            v += __shfl_down_sync(0xffffffffu, v, off);
        if (threadIdx.x == 0) { out[0] = v * (LN2 / (float)NN); g_ctr = 0; }
    }
}

// ---------------------------------------------------------------------------
extern "C" void kernel_launch(void* const* d_in, const int* in_sizes, int n_in,
                              void* d_out, int out_size)
{
    (void)in_sizes; (void)n_in; (void)out_size;
    const float* z1 = (const float*)d_in[0];
    const float* z2 = (const float*)d_in[1];
    float* out = (float*)d_out;

    static int smem_set = 0;
    const int SMEM_BYTES = 196608 + 4096;
    if (!smem_set) {
        cudaFuncSetAttribute(sim_mma_kernel,
                             cudaFuncAttributeMaxDynamicSharedMemorySize, SMEM_BYTES);
        smem_set = 1;
    }

    normalize_kernel<<<NN / 8, 256>>>(z1, z2);
    sim_mma_kernel<<<NCTA, 512, SMEM_BYTES>>>();
    loss_reduce_kernel<<<32, 256>>>(out);
}